// round 3
// baseline (speedup 1.0000x reference)
#include <cuda_runtime.h>
#include <cstdint>

// Problem constants (fixed shapes)
#define NN 50000
#define EE 800000
#define DD 100
#define RR 200
#define BB 50
#define BN_EPS 1e-5f

// -------- scratch (static device allocations; no runtime alloc allowed) -----
__device__ float g_wt[5 * DD * DD];     // transposed weights [mat][k][o], mat: 0=Ws,1=Wk,2=Wq,3=Wv,4=Wr
__device__ float g_bias[5 * DD];        // biases per mat
__device__ float g_relw[RR * DD];       // rel_w = w_comp @ relation_att
__device__ float g_proj[4L * NN * DD];  // S,K,Q,V  (mat-major)
__device__ float g_att[EE];             // per-edge attention logit
__device__ int   g_cnt[NN];             // in-degree histogram
__device__ int   g_row[NN + 1];         // CSR row starts (by dst)
__device__ int   g_cur[NN];             // scatter cursors
__device__ int   g_csrc[EE];            // CSR: src per slot
__device__ float g_catt[EE];            // CSR: att per slot
__device__ float g_npre[NN * DD];       // pre-BN node output
__device__ float g_colsum[DD];
__device__ float g_colsq[DD];

// ---------------------------------------------------------------------------
__global__ void zero_kernel() {
    int i = blockIdx.x * blockDim.x + threadIdx.x;
    for (int idx = i; idx < NN; idx += gridDim.x * blockDim.x) g_cnt[idx] = 0;
    if (i < DD) { g_colsum[i] = 0.f; g_colsq[i] = 0.f; }
}

// prep: transpose 5 weight matrices, copy biases, compute rel_w
__global__ void prep_kernel(const float* __restrict__ Ws, const float* __restrict__ bs,
                            const float* __restrict__ Wk, const float* __restrict__ bk,
                            const float* __restrict__ Wq, const float* __restrict__ bq,
                            const float* __restrict__ Wv, const float* __restrict__ bv,
                            const float* __restrict__ Wr, const float* __restrict__ br,
                            const float* __restrict__ w_comp, const float* __restrict__ rel_att) {
    int t = blockIdx.x * blockDim.x + threadIdx.x;
    if (t < 5 * DD * DD) {
        int mat = t / (DD * DD);
        int r = t % (DD * DD);
        int k = r / DD, o = r % DD;
        const float* W = (mat == 0) ? Ws : (mat == 1) ? Wk : (mat == 2) ? Wq : (mat == 3) ? Wv : Wr;
        g_wt[mat * DD * DD + k * DD + o] = W[o * DD + k];
    }
    if (t < 5 * DD) {
        int mat = t / DD, o = t % DD;
        const float* b = (mat == 0) ? bs : (mat == 1) ? bk : (mat == 2) ? bq : (mat == 3) ? bv : br;
        g_bias[t] = b[o];
    }
    if (t < RR * DD) {
        int r = t / DD, o = t % DD;
        float acc = 0.f;
#pragma unroll 5
        for (int b = 0; b < BB; b++) acc += w_comp[r * BB + b] * rel_att[b * DD + o];
        g_relw[t] = acc;
    }
}

// Node projections: out[mat][n][o] = sum_k x[n][k] * W[o][k] + b[o]
// block: 256 threads = 8 warps; 64 nodes per block; grid.y = mat (0..3)
// thread (ty=tid/32, tx=tid%32): nodes ty*8..ty*8+7, douts tx, tx+32, tx+64, tx+96(pred)
__global__ __launch_bounds__(256) void proj_kernel(const float* __restrict__ x) {
    const int mat = blockIdx.y;
    const int nb = blockIdx.x * 64;
    const int tid = threadIdx.x;
    const int ty = tid >> 5, tx = tid & 31;

    __shared__ float xs[DD][68];  // transposed x tile, padded

    for (int idx = tid; idx < 64 * DD; idx += 256) {
        int nl = idx / DD, c = idx % DD;
        int n = nb + nl;
        xs[c][nl] = (n < NN) ? x[(size_t)n * DD + c] : 0.f;
    }
    __syncthreads();

    float acc[8][4];
#pragma unroll
    for (int j = 0; j < 8; j++)
#pragma unroll
        for (int q = 0; q < 4; q++) acc[j][q] = 0.f;

    const float* wmat = g_wt + mat * DD * DD;
    const int nlb = ty * 8;

#pragma unroll 4
    for (int k = 0; k < DD; k++) {
        float w0 = wmat[k * DD + tx];
        float w1 = wmat[k * DD + tx + 32];
        float w2 = wmat[k * DD + tx + 64];
        float w3 = (tx < 4) ? wmat[k * DD + tx + 96] : 0.f;
        float4 xa = *(const float4*)&xs[k][nlb];
        float4 xb = *(const float4*)&xs[k][nlb + 4];
        float xv[8] = {xa.x, xa.y, xa.z, xa.w, xb.x, xb.y, xb.z, xb.w};
#pragma unroll
        for (int j = 0; j < 8; j++) {
            acc[j][0] = fmaf(xv[j], w0, acc[j][0]);
            acc[j][1] = fmaf(xv[j], w1, acc[j][1]);
            acc[j][2] = fmaf(xv[j], w2, acc[j][2]);
            acc[j][3] = fmaf(xv[j], w3, acc[j][3]);
        }
    }

    float b0 = g_bias[mat * DD + tx];
    float b1 = g_bias[mat * DD + tx + 32];
    float b2 = g_bias[mat * DD + tx + 64];
    float b3 = (tx < 4) ? g_bias[mat * DD + tx + 96] : 0.f;

    float* obase = g_proj + (size_t)mat * NN * DD;
#pragma unroll
    for (int j = 0; j < 8; j++) {
        int n = nb + nlb + j;
        if (n < NN) {
            float* o = obase + (size_t)n * DD;
            o[tx] = acc[j][0] + b0;
            o[tx + 32] = acc[j][1] + b1;
            o[tx + 64] = acc[j][2] + b2;
            if (tx < 4) o[tx + 96] = acc[j][3] + b3;
        }
    }
}

// Edge attention: warp per edge. att[e] = sum_d K[src,d]*relw[et,d]*Q[dst,d]
// Also histogram in-degree of dst.
__global__ __launch_bounds__(256) void att_kernel(const int* __restrict__ src,
                                                  const int* __restrict__ dst,
                                                  const int* __restrict__ et) {
    int warp = (blockIdx.x * blockDim.x + threadIdx.x) >> 5;
    int lane = threadIdx.x & 31;
    if (warp >= EE) return;
    int s = src[warp], d = dst[warp], r = et[warp];
    const float* K = g_proj + 1L * NN * DD;
    const float* Q = g_proj + 2L * NN * DD;
    float p = 0.f;
    if (lane < 25) {
        float4 kv = *(const float4*)(K + (size_t)s * DD + lane * 4);
        float4 qv = *(const float4*)(Q + (size_t)d * DD + lane * 4);
        float4 wv = *(const float4*)(g_relw + r * DD + lane * 4);
        p = kv.x * qv.x * wv.x + kv.y * qv.y * wv.y + kv.z * qv.z * wv.z + kv.w * qv.w * wv.w;
    }
#pragma unroll
    for (int o = 16; o; o >>= 1) p += __shfl_xor_sync(0xffffffffu, p, o);
    if (lane == 0) {
        g_att[warp] = p;
        atomicAdd(&g_cnt[d], 1);
    }
}

// single-block exclusive scan of g_cnt -> g_row, g_cur ; g_row[NN] = EE
__global__ void scan_kernel() {
    __shared__ int wsum[32];
    __shared__ int carry_s;
    const int tid = threadIdx.x;
    const int lane = tid & 31, wid = tid >> 5;
    if (tid == 0) carry_s = 0;
    __syncthreads();
    for (int base = 0; base < NN; base += 1024) {
        int i = base + tid;
        int v = (i < NN) ? g_cnt[i] : 0;
        int incl = v;
#pragma unroll
        for (int o = 1; o < 32; o <<= 1) {
            int t = __shfl_up_sync(0xffffffffu, incl, o);
            if (lane >= o) incl += t;
        }
        if (lane == 31) wsum[wid] = incl;
        __syncthreads();
        if (wid == 0) {
            int wv = wsum[lane];
            int wincl = wv;
#pragma unroll
            for (int o = 1; o < 32; o <<= 1) {
                int t = __shfl_up_sync(0xffffffffu, wincl, o);
                if (lane >= o) wincl += t;
            }
            wsum[lane] = wincl - wv;  // exclusive warp offsets
        }
        __syncthreads();
        int excl = carry_s + wsum[wid] + incl - v;
        if (i < NN) {
            g_row[i] = excl;
            g_cur[i] = excl;
        }
        __syncthreads();
        if (tid == 1023) carry_s = excl + v;
        __syncthreads();
    }
    if (tid == 0) g_row[NN] = carry_s;
}

__global__ void scatter_kernel(const int* __restrict__ src, const int* __restrict__ dst) {
    int e = blockIdx.x * blockDim.x + threadIdx.x;
    if (e >= EE) return;
    int d = dst[e];
    int pos = atomicAdd(&g_cur[d], 1);
    g_csrc[pos] = src[e];
    g_catt[pos] = g_att[e];
}

// warp per dst node: segment softmax + weighted V sum + gated combine
__global__ __launch_bounds__(256) void agg_kernel(const float* __restrict__ alpha) {
    int node = (blockIdx.x * blockDim.x + threadIdx.x) >> 5;
    int lane = threadIdx.x & 31;
    if (node >= NN) return;
    int s0 = g_row[node], s1 = g_row[node + 1];
    int deg = s1 - s0;
    const float* V = g_proj + 3L * NN * DD;
    const float* S = g_proj;  // mat 0
    float a = 1.f / (1.f + __expf(-alpha[0]));

    float4 acc = {0.f, 0.f, 0.f, 0.f};
    if (deg > 0) {
        float m = -1e30f;
        for (int i = lane; i < deg; i += 32) m = fmaxf(m, g_catt[s0 + i]);
#pragma unroll
        for (int o = 16; o; o >>= 1) m = fmaxf(m, __shfl_xor_sync(0xffffffffu, m, o));
        float ssum = 0.f;
        for (int i = lane; i < deg; i += 32) ssum += __expf(g_catt[s0 + i] - m);
#pragma unroll
        for (int o = 16; o; o >>= 1) ssum += __shfl_xor_sync(0xffffffffu, ssum, o);
        float inv = 1.f / ssum;
        for (int i = 0; i < deg; i++) {
            float w = __expf(g_catt[s0 + i] - m) * inv;
            int sv = g_csrc[s0 + i];
            if (lane < 25) {
                float4 v = *(const float4*)(V + (size_t)sv * DD + lane * 4);
                acc.x = fmaf(w, v.x, acc.x);
                acc.y = fmaf(w, v.y, acc.y);
                acc.z = fmaf(w, v.z, acc.z);
                acc.w = fmaf(w, v.w, acc.w);
            }
        }
    }
    if (lane < 25) {
        float4 sv = *(const float4*)(S + (size_t)node * DD + lane * 4);
        float4 o;
        float b = 1.f - a;
        o.x = a * sv.x + b * acc.x;
        o.y = a * sv.y + b * acc.y;
        o.z = a * sv.z + b * acc.z;
        o.w = a * sv.w + b * acc.w;
        *(float4*)(g_npre + (size_t)node * DD + lane * 4) = o;
    }
}

__global__ void bnstats_kernel() {
    __shared__ float ls[DD], lq[DD];
    int tid = threadIdx.x;
    if (tid < DD) { ls[tid] = 0.f; lq[tid] = 0.f; }
    __syncthreads();
    const int total = NN * DD;
    for (int idx = blockIdx.x * blockDim.x + tid; idx < total; idx += gridDim.x * blockDim.x) {
        float v = g_npre[idx];
        int c = idx % DD;
        atomicAdd(&ls[c], v);
        atomicAdd(&lq[c], v * v);
    }
    __syncthreads();
    if (tid < DD) {
        atomicAdd(&g_colsum[tid], ls[tid]);
        atomicAdd(&g_colsq[tid], lq[tid]);
    }
}

__global__ void bnapply_kernel(const float* __restrict__ gamma, const float* __restrict__ beta,
                               float* __restrict__ out) {
    int idx = blockIdx.x * blockDim.x + threadIdx.x;
    if (idx >= NN * DD) return;
    int c = idx % DD;
    const float invN = 1.f / (float)NN;
    float mu = g_colsum[c] * invN;
    float var = g_colsq[c] * invN - mu * mu;
    float inv = rsqrtf(var + BN_EPS);
    float v = (g_npre[idx] - mu) * inv * gamma[c] + beta[c];
    out[idx] = tanhf(v);
}

// r_out = r_feats @ Wr^T + br  (only the first RR rows; loop_rel row is dropped)
__global__ void rout_kernel(const float* __restrict__ r_feats, float* __restrict__ out) {
    int t = blockIdx.x * blockDim.x + threadIdx.x;
    if (t >= RR * DD) return;
    int r = t / DD, o = t % DD;
    const float* wt4 = g_wt + 4 * DD * DD;  // [k][o]
    const float* x = r_feats + r * DD;
    float acc = g_bias[4 * DD + o];
#pragma unroll 4
    for (int k = 0; k < DD; k++) acc = fmaf(x[k], wt4[k * DD + o], acc);
    out[t] = acc;
}

// ---------------------------------------------------------------------------
extern "C" void kernel_launch(void* const* d_in, const int* in_sizes, int n_in,
                              void* d_out, int out_size) {
    const float* x       = (const float*)d_in[0];
    const float* r_feats = (const float*)d_in[1];
    const int*   src     = (const int*)d_in[2];
    const int*   dst     = (const int*)d_in[3];
    const int*   et      = (const int*)d_in[4];
    // d_in[5] = norm (unused by reference)
    const float* Ws_w = (const float*)d_in[6];
    const float* Ws_b = (const float*)d_in[7];
    const float* Wk_w = (const float*)d_in[8];
    const float* Wk_b = (const float*)d_in[9];
    const float* Wq_w = (const float*)d_in[10];
    const float* Wq_b = (const float*)d_in[11];
    const float* Wv_w = (const float*)d_in[12];
    const float* Wv_b = (const float*)d_in[13];
    const float* Wr_w = (const float*)d_in[14];
    const float* Wr_b = (const float*)d_in[15];
    const float* rel_att = (const float*)d_in[16];
    const float* w_comp  = (const float*)d_in[17];
    const float* alpha   = (const float*)d_in[18];
    // d_in[19] = loop_rel (only affects the dropped row)
    const float* gamma = (const float*)d_in[20];
    const float* beta  = (const float*)d_in[21];

    float* out_n = (float*)d_out;
    float* out_r = (float*)d_out + (out_size - RR * DD);

    zero_kernel<<<128, 256>>>();
    prep_kernel<<<(5 * DD * DD + 255) / 256, 256>>>(Ws_w, Ws_b, Wk_w, Wk_b, Wq_w, Wq_b,
                                                    Wv_w, Wv_b, Wr_w, Wr_b, w_comp, rel_att);
    dim3 pg((NN + 63) / 64, 4);
    proj_kernel<<<pg, 256>>>(x);
    att_kernel<<<(EE * 32) / 256, 256>>>(src, dst, et);
    scan_kernel<<<1, 1024>>>();
    scatter_kernel<<<(EE + 255) / 256, 256>>>(src, dst);
    agg_kernel<<<(NN * 32 + 255) / 256, 256>>>(alpha);
    bnstats_kernel<<<512, 256>>>();
    bnapply_kernel<<<(NN * DD + 255) / 256, 256>>>(gamma, beta, out_n);
    rout_kernel<<<(RR * DD + 255) / 256, 256>>>(r_feats, out_r);
}

// round 4
// speedup vs baseline: 1.0048x; 1.0048x over previous
#include <cuda_runtime.h>
#include <cstdint>

// Problem constants (fixed shapes)
#define NN 50000
#define EE 800000
#define DD 100
#define RR 200
#define BB 50
#define BN_EPS 1e-5f

// -------- scratch (static device allocations; no runtime alloc allowed) -----
__device__ float g_wt[5 * DD * DD];     // transposed weights [mat][k][o], mat: 0=Ws,1=Wk,2=Wq,3=Wv,4=Wr
__device__ float g_bias[5 * DD];        // biases per mat
__device__ float g_relw[RR * DD];       // rel_w = w_comp @ relation_att
__device__ float g_proj[4L * NN * DD];  // S,K,Q,V  (mat-major)
__device__ float g_att[EE];             // per-edge attention logit
__device__ int   g_cnt[NN];             // in-degree histogram
__device__ int   g_row[NN + 1];         // CSR row starts (by dst)
__device__ int   g_cur[NN];             // scatter cursors
__device__ int   g_csrc[EE];            // CSR: src per slot
__device__ float g_catt[EE];            // CSR: att per slot
__device__ float g_npre[NN * DD];       // pre-BN node output
__device__ float g_colsum[DD];
__device__ float g_colsq[DD];

// ---------------------------------------------------------------------------
__global__ void zero_kernel() {
    int i = blockIdx.x * blockDim.x + threadIdx.x;
    for (int idx = i; idx < NN; idx += gridDim.x * blockDim.x) g_cnt[idx] = 0;
    if (i < DD) { g_colsum[i] = 0.f; g_colsq[i] = 0.f; }
}

// prep: transpose 5 weight matrices, copy biases, compute rel_w
__global__ void prep_kernel(const float* __restrict__ Ws, const float* __restrict__ bs,
                            const float* __restrict__ Wk, const float* __restrict__ bk,
                            const float* __restrict__ Wq, const float* __restrict__ bq,
                            const float* __restrict__ Wv, const float* __restrict__ bv,
                            const float* __restrict__ Wr, const float* __restrict__ br,
                            const float* __restrict__ w_comp, const float* __restrict__ rel_att) {
    int t = blockIdx.x * blockDim.x + threadIdx.x;
    if (t < 5 * DD * DD) {
        int mat = t / (DD * DD);
        int r = t % (DD * DD);
        int k = r / DD, o = r % DD;
        const float* W = (mat == 0) ? Ws : (mat == 1) ? Wk : (mat == 2) ? Wq : (mat == 3) ? Wv : Wr;
        g_wt[mat * DD * DD + k * DD + o] = W[o * DD + k];
    }
    if (t < 5 * DD) {
        int mat = t / DD, o = t % DD;
        const float* b = (mat == 0) ? bs : (mat == 1) ? bk : (mat == 2) ? bq : (mat == 3) ? bv : br;
        g_bias[t] = b[o];
    }
    if (t < RR * DD) {
        int r = t / DD, o = t % DD;
        float acc = 0.f;
#pragma unroll 5
        for (int b = 0; b < BB; b++) acc += w_comp[r * BB + b] * rel_att[b * DD + o];
        g_relw[t] = acc;
    }
}

// Node projections: out[mat][n][o] = sum_k x[n][k] * W[o][k] + b[o]
// block: 256 threads = 8 warps; 64 nodes per block; grid.y = mat (0..3)
// thread (ty=tid/32, tx=tid%32): nodes ty*8..ty*8+7, douts tx, tx+32, tx+64, tx+96(pred)
__global__ __launch_bounds__(256) void proj_kernel(const float* __restrict__ x) {
    const int mat = blockIdx.y;
    const int nb = blockIdx.x * 64;
    const int tid = threadIdx.x;
    const int ty = tid >> 5, tx = tid & 31;

    __shared__ float xs[DD][68];  // transposed x tile, padded

    for (int idx = tid; idx < 64 * DD; idx += 256) {
        int nl = idx / DD, c = idx % DD;
        int n = nb + nl;
        xs[c][nl] = (n < NN) ? x[(size_t)n * DD + c] : 0.f;
    }
    __syncthreads();

    float acc[8][4];
#pragma unroll
    for (int j = 0; j < 8; j++)
#pragma unroll
        for (int q = 0; q < 4; q++) acc[j][q] = 0.f;

    const float* wmat = g_wt + mat * DD * DD;
    const int nlb = ty * 8;

#pragma unroll 4
    for (int k = 0; k < DD; k++) {
        float w0 = wmat[k * DD + tx];
        float w1 = wmat[k * DD + tx + 32];
        float w2 = wmat[k * DD + tx + 64];
        float w3 = (tx < 4) ? wmat[k * DD + tx + 96] : 0.f;
        float4 xa = *(const float4*)&xs[k][nlb];
        float4 xb = *(const float4*)&xs[k][nlb + 4];
        float xv[8] = {xa.x, xa.y, xa.z, xa.w, xb.x, xb.y, xb.z, xb.w};
#pragma unroll
        for (int j = 0; j < 8; j++) {
            acc[j][0] = fmaf(xv[j], w0, acc[j][0]);
            acc[j][1] = fmaf(xv[j], w1, acc[j][1]);
            acc[j][2] = fmaf(xv[j], w2, acc[j][2]);
            acc[j][3] = fmaf(xv[j], w3, acc[j][3]);
        }
    }

    float b0 = g_bias[mat * DD + tx];
    float b1 = g_bias[mat * DD + tx + 32];
    float b2 = g_bias[mat * DD + tx + 64];
    float b3 = (tx < 4) ? g_bias[mat * DD + tx + 96] : 0.f;

    float* obase = g_proj + (size_t)mat * NN * DD;
#pragma unroll
    for (int j = 0; j < 8; j++) {
        int n = nb + nlb + j;
        if (n < NN) {
            float* o = obase + (size_t)n * DD;
            o[tx] = acc[j][0] + b0;
            o[tx + 32] = acc[j][1] + b1;
            o[tx + 64] = acc[j][2] + b2;
            if (tx < 4) o[tx + 96] = acc[j][3] + b3;
        }
    }
}

// Edge attention: warp per edge. att[e] = sum_d K[src,d]*relw[et,d]*Q[dst,d]
// Also histogram in-degree of dst.
__global__ __launch_bounds__(256) void att_kernel(const int* __restrict__ src,
                                                  const int* __restrict__ dst,
                                                  const int* __restrict__ et) {
    int warp = (blockIdx.x * blockDim.x + threadIdx.x) >> 5;
    int lane = threadIdx.x & 31;
    if (warp >= EE) return;
    int s = src[warp], d = dst[warp], r = et[warp];
    const float* K = g_proj + 1L * NN * DD;
    const float* Q = g_proj + 2L * NN * DD;
    float p = 0.f;
    if (lane < 25) {
        float4 kv = *(const float4*)(K + (size_t)s * DD + lane * 4);
        float4 qv = *(const float4*)(Q + (size_t)d * DD + lane * 4);
        float4 wv = *(const float4*)(g_relw + r * DD + lane * 4);
        p = kv.x * qv.x * wv.x + kv.y * qv.y * wv.y + kv.z * qv.z * wv.z + kv.w * qv.w * wv.w;
    }
#pragma unroll
    for (int o = 16; o; o >>= 1) p += __shfl_xor_sync(0xffffffffu, p, o);
    if (lane == 0) {
        g_att[warp] = p;
        atomicAdd(&g_cnt[d], 1);
    }
}

// single-block exclusive scan of g_cnt -> g_row, g_cur ; g_row[NN] = EE
__global__ void scan_kernel() {
    __shared__ int wsum[32];
    __shared__ int carry_s;
    const int tid = threadIdx.x;
    const int lane = tid & 31, wid = tid >> 5;
    if (tid == 0) carry_s = 0;
    __syncthreads();
    for (int base = 0; base < NN; base += 1024) {
        int i = base + tid;
        int v = (i < NN) ? g_cnt[i] : 0;
        int incl = v;
#pragma unroll
        for (int o = 1; o < 32; o <<= 1) {
            int t = __shfl_up_sync(0xffffffffu, incl, o);
            if (lane >= o) incl += t;
        }
        if (lane == 31) wsum[wid] = incl;
        __syncthreads();
        if (wid == 0) {
            int wv = wsum[lane];
            int wincl = wv;
#pragma unroll
            for (int o = 1; o < 32; o <<= 1) {
                int t = __shfl_up_sync(0xffffffffu, wincl, o);
                if (lane >= o) wincl += t;
            }
            wsum[lane] = wincl - wv;  // exclusive warp offsets
        }
        __syncthreads();
        int excl = carry_s + wsum[wid] + incl - v;
        if (i < NN) {
            g_row[i] = excl;
            g_cur[i] = excl;
        }
        __syncthreads();
        if (tid == 1023) carry_s = excl + v;
        __syncthreads();
    }
    if (tid == 0) g_row[NN] = carry_s;
}

__global__ void scatter_kernel(const int* __restrict__ src, const int* __restrict__ dst) {
    int e = blockIdx.x * blockDim.x + threadIdx.x;
    if (e >= EE) return;
    int d = dst[e];
    int pos = atomicAdd(&g_cur[d], 1);
    g_csrc[pos] = src[e];
    g_catt[pos] = g_att[e];
}

// warp per dst node: segment softmax + weighted V sum + gated combine
__global__ __launch_bounds__(256) void agg_kernel(const float* __restrict__ alpha) {
    int node = (blockIdx.x * blockDim.x + threadIdx.x) >> 5;
    int lane = threadIdx.x & 31;
    if (node >= NN) return;
    int s0 = g_row[node], s1 = g_row[node + 1];
    int deg = s1 - s0;
    const float* V = g_proj + 3L * NN * DD;
    const float* S = g_proj;  // mat 0
    float a = 1.f / (1.f + __expf(-alpha[0]));

    float4 acc = {0.f, 0.f, 0.f, 0.f};
    if (deg > 0) {
        float m = -1e30f;
        for (int i = lane; i < deg; i += 32) m = fmaxf(m, g_catt[s0 + i]);
#pragma unroll
        for (int o = 16; o; o >>= 1) m = fmaxf(m, __shfl_xor_sync(0xffffffffu, m, o));
        float ssum = 0.f;
        for (int i = lane; i < deg; i += 32) ssum += __expf(g_catt[s0 + i] - m);
#pragma unroll
        for (int o = 16; o; o >>= 1) ssum += __shfl_xor_sync(0xffffffffu, ssum, o);
        float inv = 1.f / ssum;
        for (int i = 0; i < deg; i++) {
            float w = __expf(g_catt[s0 + i] - m) * inv;
            int sv = g_csrc[s0 + i];
            if (lane < 25) {
                float4 v = *(const float4*)(V + (size_t)sv * DD + lane * 4);
                acc.x = fmaf(w, v.x, acc.x);
                acc.y = fmaf(w, v.y, acc.y);
                acc.z = fmaf(w, v.z, acc.z);
                acc.w = fmaf(w, v.w, acc.w);
            }
        }
    }
    if (lane < 25) {
        float4 sv = *(const float4*)(S + (size_t)node * DD + lane * 4);
        float4 o;
        float b = 1.f - a;
        o.x = a * sv.x + b * acc.x;
        o.y = a * sv.y + b * acc.y;
        o.z = a * sv.z + b * acc.z;
        o.w = a * sv.w + b * acc.w;
        *(float4*)(g_npre + (size_t)node * DD + lane * 4) = o;
    }
}

__global__ void bnstats_kernel() {
    __shared__ float ls[DD], lq[DD];
    int tid = threadIdx.x;
    if (tid < DD) { ls[tid] = 0.f; lq[tid] = 0.f; }
    __syncthreads();
    const int total = NN * DD;
    for (int idx = blockIdx.x * blockDim.x + tid; idx < total; idx += gridDim.x * blockDim.x) {
        float v = g_npre[idx];
        int c = idx % DD;
        atomicAdd(&ls[c], v);
        atomicAdd(&lq[c], v * v);
    }
    __syncthreads();
    if (tid < DD) {
        atomicAdd(&g_colsum[tid], ls[tid]);
        atomicAdd(&g_colsq[tid], lq[tid]);
    }
}

__global__ void bnapply_kernel(const float* __restrict__ gamma, const float* __restrict__ beta,
                               float* __restrict__ out) {
    int idx = blockIdx.x * blockDim.x + threadIdx.x;
    if (idx >= NN * DD) return;
    int c = idx % DD;
    const float invN = 1.f / (float)NN;
    float mu = g_colsum[c] * invN;
    float var = g_colsq[c] * invN - mu * mu;
    float inv = rsqrtf(var + BN_EPS);
    float v = (g_npre[idx] - mu) * inv * gamma[c] + beta[c];
    out[idx] = tanhf(v);
}

// r_out = r_feats @ Wr^T + br  (only the first RR rows; loop_rel row is dropped)
__global__ void rout_kernel(const float* __restrict__ r_feats, float* __restrict__ out) {
    int t = blockIdx.x * blockDim.x + threadIdx.x;
    if (t >= RR * DD) return;
    int r = t / DD, o = t % DD;
    const float* wt4 = g_wt + 4 * DD * DD;  // [k][o]
    const float* x = r_feats + r * DD;
    float acc = g_bias[4 * DD + o];
#pragma unroll 4
    for (int k = 0; k < DD; k++) acc = fmaf(x[k], wt4[k * DD + o], acc);
    out[t] = acc;
}

// ---------------------------------------------------------------------------
extern "C" void kernel_launch(void* const* d_in, const int* in_sizes, int n_in,
                              void* d_out, int out_size) {
    const float* x       = (const float*)d_in[0];
    const float* r_feats = (const float*)d_in[1];
    const int*   src     = (const int*)d_in[2];
    const int*   dst     = (const int*)d_in[3];
    const int*   et      = (const int*)d_in[4];
    // d_in[5] = norm (unused by reference)
    const float* Ws_w = (const float*)d_in[6];
    const float* Ws_b = (const float*)d_in[7];
    const float* Wk_w = (const float*)d_in[8];
    const float* Wk_b = (const float*)d_in[9];
    const float* Wq_w = (const float*)d_in[10];
    const float* Wq_b = (const float*)d_in[11];
    const float* Wv_w = (const float*)d_in[12];
    const float* Wv_b = (const float*)d_in[13];
    const float* Wr_w = (const float*)d_in[14];
    const float* Wr_b = (const float*)d_in[15];
    const float* rel_att = (const float*)d_in[16];
    const float* w_comp  = (const float*)d_in[17];
    const float* alpha   = (const float*)d_in[18];
    // d_in[19] = loop_rel (only affects the dropped row)
    const float* gamma = (const float*)d_in[20];
    const float* beta  = (const float*)d_in[21];

    float* out_n = (float*)d_out;
    float* out_r = (float*)d_out + (out_size - RR * DD);

    zero_kernel<<<128, 256>>>();
    prep_kernel<<<(5 * DD * DD + 255) / 256, 256>>>(Ws_w, Ws_b, Wk_w, Wk_b, Wq_w, Wq_b,
                                                    Wv_w, Wv_b, Wr_w, Wr_b, w_comp, rel_att);
    dim3 pg((NN + 63) / 64, 4);
    proj_kernel<<<pg, 256>>>(x);
    att_kernel<<<(EE * 32) / 256, 256>>>(src, dst, et);
    scan_kernel<<<1, 1024>>>();
    scatter_kernel<<<(EE + 255) / 256, 256>>>(src, dst);
    agg_kernel<<<(NN * 32 + 255) / 256, 256>>>(alpha);
    bnstats_kernel<<<512, 256>>>();
    bnapply_kernel<<<(NN * DD + 255) / 256, 256>>>(gamma, beta, out_n);
    rout_kernel<<<(RR * DD + 255) / 256, 256>>>(r_feats, out_r);
}

// round 5
// speedup vs baseline: 1.0591x; 1.0541x over previous
#include <cuda_runtime.h>
#include <cstdint>

// Problem constants (fixed shapes)
#define NN 50000
#define EE 800000
#define DD 100
#define RR 200
#define BB 50
#define BN_EPS 1e-5f
#define CAP 96   // per-warp smem logit buffer; deg>CAP spills to g_catt

// -------- scratch (static device allocations; no runtime alloc allowed) -----
__device__ float g_wt[5 * DD * DD];     // transposed weights [mat][k][o], 0=Ws,1=Wk,2=Wq,3=Wv,4=Wr
__device__ float g_bias[5 * DD];
__device__ float g_relw[RR * DD];       // rel_w = w_comp @ relation_att
__device__ float g_proj[4L * NN * DD];  // S,K,Q,V (mat-major)
__device__ int   g_cnt[NN];             // in-degree histogram
__device__ int   g_row[NN + 1];         // CSR row starts (by dst)
__device__ int   g_cur[NN];             // scatter cursors
__device__ int   g_csrc[EE];            // CSR: src per slot
__device__ int   g_cet[EE];             // CSR: etype per slot
__device__ float g_catt[EE];            // spill buffer for logits (deg > CAP)
__device__ float g_npre[NN * DD];       // pre-BN node output
__device__ float g_colsum[DD];
__device__ float g_colsq[DD];

// ---------------------------------------------------------------------------
__global__ void zero_kernel() {
    int i = blockIdx.x * blockDim.x + threadIdx.x;
    for (int idx = i; idx < NN; idx += gridDim.x * blockDim.x) g_cnt[idx] = 0;
    if (i < DD) { g_colsum[i] = 0.f; g_colsq[i] = 0.f; }
}

// prep: transpose 5 weight matrices, copy biases, compute rel_w
__global__ void prep_kernel(const float* __restrict__ Ws, const float* __restrict__ bs,
                            const float* __restrict__ Wk, const float* __restrict__ bk,
                            const float* __restrict__ Wq, const float* __restrict__ bq,
                            const float* __restrict__ Wv, const float* __restrict__ bv,
                            const float* __restrict__ Wr, const float* __restrict__ br,
                            const float* __restrict__ w_comp, const float* __restrict__ rel_att) {
    int t = blockIdx.x * blockDim.x + threadIdx.x;
    if (t < 5 * DD * DD) {
        int mat = t / (DD * DD);
        int r = t % (DD * DD);
        int k = r / DD, o = r % DD;
        const float* W = (mat == 0) ? Ws : (mat == 1) ? Wk : (mat == 2) ? Wq : (mat == 3) ? Wv : Wr;
        g_wt[mat * DD * DD + k * DD + o] = W[o * DD + k];
    }
    if (t < 5 * DD) {
        int mat = t / DD, o = t % DD;
        const float* b = (mat == 0) ? bs : (mat == 1) ? bk : (mat == 2) ? bq : (mat == 3) ? bv : br;
        g_bias[t] = b[o];
    }
    if (t < RR * DD) {
        int r = t / DD, o = t % DD;
        float acc = 0.f;
#pragma unroll 5
        for (int b = 0; b < BB; b++) acc += w_comp[r * BB + b] * rel_att[b * DD + o];
        g_relw[t] = acc;
    }
}

// Node projections: out[mat][n][o] = sum_k x[n][k] * W[o][k] + b[o]
__global__ __launch_bounds__(256) void proj_kernel(const float* __restrict__ x) {
    const int mat = blockIdx.y;
    const int nb = blockIdx.x * 64;
    const int tid = threadIdx.x;
    const int ty = tid >> 5, tx = tid & 31;

    __shared__ float xs[DD][68];

    for (int idx = tid; idx < 64 * DD; idx += 256) {
        int nl = idx / DD, c = idx % DD;
        int n = nb + nl;
        xs[c][nl] = (n < NN) ? x[(size_t)n * DD + c] : 0.f;
    }
    __syncthreads();

    float acc[8][4];
#pragma unroll
    for (int j = 0; j < 8; j++)
#pragma unroll
        for (int q = 0; q < 4; q++) acc[j][q] = 0.f;

    const float* wmat = g_wt + mat * DD * DD;
    const int nlb = ty * 8;

#pragma unroll 4
    for (int k = 0; k < DD; k++) {
        float w0 = wmat[k * DD + tx];
        float w1 = wmat[k * DD + tx + 32];
        float w2 = wmat[k * DD + tx + 64];
        float w3 = (tx < 4) ? wmat[k * DD + tx + 96] : 0.f;
        float4 xa = *(const float4*)&xs[k][nlb];
        float4 xb = *(const float4*)&xs[k][nlb + 4];
        float xv[8] = {xa.x, xa.y, xa.z, xa.w, xb.x, xb.y, xb.z, xb.w};
#pragma unroll
        for (int j = 0; j < 8; j++) {
            acc[j][0] = fmaf(xv[j], w0, acc[j][0]);
            acc[j][1] = fmaf(xv[j], w1, acc[j][1]);
            acc[j][2] = fmaf(xv[j], w2, acc[j][2]);
            acc[j][3] = fmaf(xv[j], w3, acc[j][3]);
        }
    }

    float b0 = g_bias[mat * DD + tx];
    float b1 = g_bias[mat * DD + tx + 32];
    float b2 = g_bias[mat * DD + tx + 64];
    float b3 = (tx < 4) ? g_bias[mat * DD + tx + 96] : 0.f;

    float* obase = g_proj + (size_t)mat * NN * DD;
#pragma unroll
    for (int j = 0; j < 8; j++) {
        int n = nb + nlb + j;
        if (n < NN) {
            float* o = obase + (size_t)n * DD;
            o[tx] = acc[j][0] + b0;
            o[tx + 32] = acc[j][1] + b1;
            o[tx + 64] = acc[j][2] + b2;
            if (tx < 4) o[tx + 96] = acc[j][3] + b3;
        }
    }
}

// in-degree histogram
__global__ void hist_kernel(const int* __restrict__ dst) {
    int e = blockIdx.x * blockDim.x + threadIdx.x;
    if (e < EE) atomicAdd(&g_cnt[dst[e]], 1);
}

// single-block exclusive scan of g_cnt -> g_row, g_cur ; g_row[NN] = EE
__global__ void scan_kernel() {
    __shared__ int wsum[32];
    __shared__ int carry_s;
    const int tid = threadIdx.x;
    const int lane = tid & 31, wid = tid >> 5;
    if (tid == 0) carry_s = 0;
    __syncthreads();
    for (int base = 0; base < NN; base += 1024) {
        int i = base + tid;
        int v = (i < NN) ? g_cnt[i] : 0;
        int incl = v;
#pragma unroll
        for (int o = 1; o < 32; o <<= 1) {
            int t = __shfl_up_sync(0xffffffffu, incl, o);
            if (lane >= o) incl += t;
        }
        if (lane == 31) wsum[wid] = incl;
        __syncthreads();
        if (wid == 0) {
            int wv = wsum[lane];
            int wincl = wv;
#pragma unroll
            for (int o = 1; o < 32; o <<= 1) {
                int t = __shfl_up_sync(0xffffffffu, wincl, o);
                if (lane >= o) wincl += t;
            }
            wsum[lane] = wincl - wv;
        }
        __syncthreads();
        int excl = carry_s + wsum[wid] + incl - v;
        if (i < NN) {
            g_row[i] = excl;
            g_cur[i] = excl;
        }
        __syncthreads();
        if (tid == 1023) carry_s = excl + v;
        __syncthreads();
    }
    if (tid == 0) g_row[NN] = carry_s;
}

__global__ void scatter_kernel(const int* __restrict__ src, const int* __restrict__ dst,
                               const int* __restrict__ et) {
    int e = blockIdx.x * blockDim.x + threadIdx.x;
    if (e >= EE) return;
    int d = dst[e];
    int pos = atomicAdd(&g_cur[d], 1);
    g_csrc[pos] = src[e];
    g_cet[pos] = et[e];
}

// Fused: per-warp per-dst: edge logits (K*relw*Q) + segment softmax + weighted V
// sum + gated combine + BN-stat accumulation.
__global__ __launch_bounds__(256) void fused_agg_kernel(const float* __restrict__ alpha) {
    __shared__ float satt[8][CAP];
    __shared__ float bsum[DD], bsq[DD];
    const int tid = threadIdx.x;
    if (tid < DD) { bsum[tid] = 0.f; bsq[tid] = 0.f; }
    __syncthreads();

    const int wid = tid >> 5, lane = tid & 31;
    const int node = blockIdx.x * 8 + wid;
    const bool active = (node < NN);
    const bool dl = (lane < 25);

    const float* S = g_proj;
    const float* K = g_proj + 1L * NN * DD;
    const float* Q = g_proj + 2L * NN * DD;
    const float* V = g_proj + 3L * NN * DD;

    float a = 1.f / (1.f + __expf(-alpha[0]));
    float4 acc = {0.f, 0.f, 0.f, 0.f};

    if (active) {
        const int s0 = g_row[node];
        const int deg = g_row[node + 1] - s0;

        float4 qv = {0.f, 0.f, 0.f, 0.f};
        if (dl) qv = *(const float4*)(Q + (size_t)node * DD + lane * 4);

        if (deg > 0) {
            float m = -1e30f;
            int i = 0;
            for (; i + 1 < deg; i += 2) {
                int sA = g_csrc[s0 + i], rA = g_cet[s0 + i];
                int sB = g_csrc[s0 + i + 1], rB = g_cet[s0 + i + 1];
                float pA = 0.f, pB = 0.f;
                if (dl) {
                    float4 kA = *(const float4*)(K + (size_t)sA * DD + lane * 4);
                    float4 wA = *(const float4*)(g_relw + rA * DD + lane * 4);
                    float4 kB = *(const float4*)(K + (size_t)sB * DD + lane * 4);
                    float4 wB = *(const float4*)(g_relw + rB * DD + lane * 4);
                    pA = kA.x * wA.x * qv.x + kA.y * wA.y * qv.y +
                         kA.z * wA.z * qv.z + kA.w * wA.w * qv.w;
                    pB = kB.x * wB.x * qv.x + kB.y * wB.y * qv.y +
                         kB.z * wB.z * qv.z + kB.w * wB.w * qv.w;
                }
#pragma unroll
                for (int o = 16; o; o >>= 1) {
                    pA += __shfl_xor_sync(0xffffffffu, pA, o);
                    pB += __shfl_xor_sync(0xffffffffu, pB, o);
                }
                m = fmaxf(m, fmaxf(pA, pB));
                if (lane == 0) {
                    if (i < CAP) satt[wid][i] = pA; else g_catt[s0 + i] = pA;
                    if (i + 1 < CAP) satt[wid][i + 1] = pB; else g_catt[s0 + i + 1] = pB;
                }
            }
            if (i < deg) {
                int sA = g_csrc[s0 + i], rA = g_cet[s0 + i];
                float pA = 0.f;
                if (dl) {
                    float4 kA = *(const float4*)(K + (size_t)sA * DD + lane * 4);
                    float4 wA = *(const float4*)(g_relw + rA * DD + lane * 4);
                    pA = kA.x * wA.x * qv.x + kA.y * wA.y * qv.y +
                         kA.z * wA.z * qv.z + kA.w * wA.w * qv.w;
                }
#pragma unroll
                for (int o = 16; o; o >>= 1) pA += __shfl_xor_sync(0xffffffffu, pA, o);
                m = fmaxf(m, pA);
                if (lane == 0) {
                    if (i < CAP) satt[wid][i] = pA; else g_catt[s0 + i] = pA;
                }
            }
            __syncwarp();

            // denominator
            float ssum = 0.f;
            for (int j = lane; j < deg; j += 32) {
                float av = (j < CAP) ? satt[wid][j] : g_catt[s0 + j];
                ssum += __expf(av - m);
            }
#pragma unroll
            for (int o = 16; o; o >>= 1) ssum += __shfl_xor_sync(0xffffffffu, ssum, o);
            float inv = 1.f / ssum;

            // weighted V accumulation, 2-way unrolled for MLP
            int j = 0;
            for (; j + 1 < deg; j += 2) {
                float aA = (j < CAP) ? satt[wid][j] : g_catt[s0 + j];
                float aB = (j + 1 < CAP) ? satt[wid][j + 1] : g_catt[s0 + j + 1];
                float wA = __expf(aA - m) * inv;
                float wB = __expf(aB - m) * inv;
                int sA = g_csrc[s0 + j];
                int sB = g_csrc[s0 + j + 1];
                if (dl) {
                    float4 vA = *(const float4*)(V + (size_t)sA * DD + lane * 4);
                    float4 vB = *(const float4*)(V + (size_t)sB * DD + lane * 4);
                    acc.x = fmaf(wA, vA.x, fmaf(wB, vB.x, acc.x));
                    acc.y = fmaf(wA, vA.y, fmaf(wB, vB.y, acc.y));
                    acc.z = fmaf(wA, vA.z, fmaf(wB, vB.z, acc.z));
                    acc.w = fmaf(wA, vA.w, fmaf(wB, vB.w, acc.w));
                }
            }
            if (j < deg) {
                float aA = (j < CAP) ? satt[wid][j] : g_catt[s0 + j];
                float wA = __expf(aA - m) * inv;
                int sA = g_csrc[s0 + j];
                if (dl) {
                    float4 vA = *(const float4*)(V + (size_t)sA * DD + lane * 4);
                    acc.x = fmaf(wA, vA.x, acc.x);
                    acc.y = fmaf(wA, vA.y, acc.y);
                    acc.z = fmaf(wA, vA.z, acc.z);
                    acc.w = fmaf(wA, vA.w, acc.w);
                }
            }
        }

        if (dl) {
            float4 sv = *(const float4*)(S + (size_t)node * DD + lane * 4);
            float b = 1.f - a;
            float4 o;
            o.x = a * sv.x + b * acc.x;
            o.y = a * sv.y + b * acc.y;
            o.z = a * sv.z + b * acc.z;
            o.w = a * sv.w + b * acc.w;
            *(float4*)(g_npre + (size_t)node * DD + lane * 4) = o;
            int c = lane * 4;
            atomicAdd(&bsum[c + 0], o.x); atomicAdd(&bsq[c + 0], o.x * o.x);
            atomicAdd(&bsum[c + 1], o.y); atomicAdd(&bsq[c + 1], o.y * o.y);
            atomicAdd(&bsum[c + 2], o.z); atomicAdd(&bsq[c + 2], o.z * o.z);
            atomicAdd(&bsum[c + 3], o.w); atomicAdd(&bsq[c + 3], o.w * o.w);
        }
    }

    __syncthreads();
    if (tid < DD) {
        atomicAdd(&g_colsum[tid], bsum[tid]);
        atomicAdd(&g_colsq[tid], bsq[tid]);
    }
}

__global__ void bnapply_kernel(const float* __restrict__ gamma, const float* __restrict__ beta,
                               float* __restrict__ out) {
    int idx = blockIdx.x * blockDim.x + threadIdx.x;
    if (idx >= NN * DD) return;
    int c = idx % DD;
    const float invN = 1.f / (float)NN;
    float mu = g_colsum[c] * invN;
    float var = g_colsq[c] * invN - mu * mu;
    float inv = rsqrtf(var + BN_EPS);
    float v = (g_npre[idx] - mu) * inv * gamma[c] + beta[c];
    out[idx] = tanhf(v);
}

// r_out = r_feats @ Wr^T + br
__global__ void rout_kernel(const float* __restrict__ r_feats, float* __restrict__ out) {
    int t = blockIdx.x * blockDim.x + threadIdx.x;
    if (t >= RR * DD) return;
    int r = t / DD, o = t % DD;
    const float* wt4 = g_wt + 4 * DD * DD;
    const float* x = r_feats + r * DD;
    float acc = g_bias[4 * DD + o];
#pragma unroll 4
    for (int k = 0; k < DD; k++) acc = fmaf(x[k], wt4[k * DD + o], acc);
    out[t] = acc;
}

// ---------------------------------------------------------------------------
extern "C" void kernel_launch(void* const* d_in, const int* in_sizes, int n_in,
                              void* d_out, int out_size) {
    const float* x       = (const float*)d_in[0];
    const float* r_feats = (const float*)d_in[1];
    const int*   src     = (const int*)d_in[2];
    const int*   dst     = (const int*)d_in[3];
    const int*   et      = (const int*)d_in[4];
    // d_in[5] = norm (unused by reference)
    const float* Ws_w = (const float*)d_in[6];
    const float* Ws_b = (const float*)d_in[7];
    const float* Wk_w = (const float*)d_in[8];
    const float* Wk_b = (const float*)d_in[9];
    const float* Wq_w = (const float*)d_in[10];
    const float* Wq_b = (const float*)d_in[11];
    const float* Wv_w = (const float*)d_in[12];
    const float* Wv_b = (const float*)d_in[13];
    const float* Wr_w = (const float*)d_in[14];
    const float* Wr_b = (const float*)d_in[15];
    const float* rel_att = (const float*)d_in[16];
    const float* w_comp  = (const float*)d_in[17];
    const float* alpha   = (const float*)d_in[18];
    // d_in[19] = loop_rel (only affects the dropped row)
    const float* gamma = (const float*)d_in[20];
    const float* beta  = (const float*)d_in[21];

    float* out_n = (float*)d_out;
    float* out_r = (float*)d_out + (out_size - RR * DD);

    zero_kernel<<<128, 256>>>();
    prep_kernel<<<(5 * DD * DD + 255) / 256, 256>>>(Ws_w, Ws_b, Wk_w, Wk_b, Wq_w, Wq_b,
                                                    Wv_w, Wv_b, Wr_w, Wr_b, w_comp, rel_att);
    hist_kernel<<<(EE + 255) / 256, 256>>>(dst);
    dim3 pg((NN + 63) / 64, 4);
    proj_kernel<<<pg, 256>>>(x);
    scan_kernel<<<1, 1024>>>();
    scatter_kernel<<<(EE + 255) / 256, 256>>>(src, dst, et);
    fused_agg_kernel<<<(NN + 7) / 8, 256>>>(alpha);
    bnapply_kernel<<<(NN * DD + 255) / 256, 256>>>(gamma, beta, out_n);
    rout_kernel<<<(RR * DD + 255) / 256, 256>>>(r_feats, out_r);
}

// round 7
// speedup vs baseline: 1.2304x; 1.1618x over previous
#include <cuda_runtime.h>
#include <cstdint>

// Problem constants (fixed shapes)
#define NN 50000
#define EE 800000
#define DD 100
#define RR 200
#define BB 50
#define BN_EPS 1e-5f
#define CAP 96   // per-warp smem logit buffer; deg>CAP spills to g_catt
#define KC 20    // k-chunk for proj weight staging (100 = 5 chunks) — fits 48KB static smem

// -------- scratch (static device allocations; no runtime alloc allowed) -----
__device__ float g_wt[5 * DD * DD];      // transposed weights [mat][k][o] (only mat4=Wr used now)
__device__ float g_bias[5 * DD];
__device__ float g_wstack[DD * 512];     // stacked proj weights: [k][mat*100+o], zero-padded cols 400..511
__device__ float g_bstack[512];          // stacked biases, zero-padded
__device__ float g_relw[RR * DD];        // rel_w = w_comp @ relation_att
__device__ float g_proj[4L * NN * DD];   // S,K,Q,V (mat-major)
__device__ int   g_cnt[NN];              // in-degree histogram
__device__ int   g_row[NN + 1];          // CSR row starts (by dst)
__device__ int   g_cur[NN];              // scatter cursors
__device__ int   g_csrc[EE];             // CSR: src per slot
__device__ int   g_cet[EE];              // CSR: etype per slot
__device__ float g_catt[EE];             // spill buffer for logits (deg > CAP)
__device__ float g_npre[NN * DD];        // pre-BN node output
__device__ float g_colsum[DD];
__device__ float g_colsq[DD];

// ---------------------------------------------------------------------------
__global__ void zero_kernel() {
    int i = blockIdx.x * blockDim.x + threadIdx.x;
    for (int idx = i; idx < NN; idx += gridDim.x * blockDim.x) g_cnt[idx] = 0;
    if (i < DD) { g_colsum[i] = 0.f; g_colsq[i] = 0.f; }
}

// prep: build stacked/transposed proj weights + Wr transpose + biases + rel_w
__global__ void prep_kernel(const float* __restrict__ Ws, const float* __restrict__ bs,
                            const float* __restrict__ Wk, const float* __restrict__ bk,
                            const float* __restrict__ Wq, const float* __restrict__ bq,
                            const float* __restrict__ Wv, const float* __restrict__ bv,
                            const float* __restrict__ Wr, const float* __restrict__ br,
                            const float* __restrict__ w_comp, const float* __restrict__ rel_att) {
    int t = blockIdx.x * blockDim.x + threadIdx.x;
    // stacked proj weights: wstack[k][c], c = mat*100+o for mat in 0..3
    if (t < DD * 512) {
        int k = t / 512, c = t % 512;
        float val = 0.f;
        if (c < 400) {
            int mat = c / DD, o = c % DD;
            const float* W = (mat == 0) ? Ws : (mat == 1) ? Wk : (mat == 2) ? Wq : Wv;
            val = W[o * DD + k];
        }
        g_wstack[k * 512 + c] = val;
    }
    if (t < 512) {
        float val = 0.f;
        if (t < 400) {
            int mat = t / DD, o = t % DD;
            const float* b = (mat == 0) ? bs : (mat == 1) ? bk : (mat == 2) ? bq : bv;
            val = b[o];
        }
        g_bstack[t] = val;
    }
    // Wr transpose (for rout) + its bias
    if (t < DD * DD) {
        int k = t / DD, o = t % DD;
        g_wt[4 * DD * DD + k * DD + o] = Wr[o * DD + k];
    }
    if (t < DD) g_bias[4 * DD + t] = br[t];
    if (t < RR * DD) {
        int r = t / DD, o = t % DD;
        float acc = 0.f;
#pragma unroll 5
        for (int b = 0; b < BB; b++) acc += w_comp[r * BB + b] * rel_att[b * DD + o];
        g_relw[t] = acc;
    }
}

// Fused 4-matrix projection GEMM: [NN x 100] @ [100 x 400(+pad 416)]
// Block: 256 threads (8 warps), 32 nodes per block.
// Warp ty handles nodes ty*4..ty*4+3; lane tx handles outs tx + 32*i, i=0..12.
__global__ __launch_bounds__(256, 2) void proj_kernel(const float* __restrict__ x) {
    const int nb = blockIdx.x * 32;
    const int tid = threadIdx.x;
    const int ty = tid >> 5, tx = tid & 31;

    __shared__ float xs[DD][36];       // transposed x tile (32 nodes + pad)  = 14400 B
    __shared__ float ws[KC][416];      // weight chunk, 416 cols              = 33280 B

    // load x tile (each node row coalesced)
    for (int idx = tid; idx < 32 * DD; idx += 256) {
        int nl = idx / DD, c = idx % DD;
        int n = nb + nl;
        xs[c][nl] = (n < NN) ? x[(size_t)n * DD + c] : 0.f;
    }

    float acc[4][13];
#pragma unroll
    for (int j = 0; j < 4; j++)
#pragma unroll
        for (int i = 0; i < 13; i++) acc[j][i] = 0.f;

    for (int kc = 0; kc < DD; kc += KC) {
        // stage weight chunk: rows kc..kc+KC-1, cols 0..415 (float4 coalesced)
        __syncthreads();
        for (int idx = tid; idx < KC * 104; idx += 256) {
            int row = idx / 104, c4 = idx % 104;
            *(float4*)&ws[row][c4 * 4] =
                *(const float4*)&g_wstack[(kc + row) * 512 + c4 * 4];
        }
        __syncthreads();

#pragma unroll 5
        for (int kk = 0; kk < KC; kk++) {
            const int k = kc + kk;
            float4 xv = *(const float4*)&xs[k][ty * 4];   // broadcast within warp
            float wv[13];
#pragma unroll
            for (int i = 0; i < 13; i++) wv[i] = ws[kk][tx + 32 * i];  // conflict-free
#pragma unroll
            for (int i = 0; i < 13; i++) {
                acc[0][i] = fmaf(xv.x, wv[i], acc[0][i]);
                acc[1][i] = fmaf(xv.y, wv[i], acc[1][i]);
                acc[2][i] = fmaf(xv.z, wv[i], acc[2][i]);
                acc[3][i] = fmaf(xv.w, wv[i], acc[3][i]);
            }
        }
    }

    // epilogue: scatter into g_proj[mat][n][o]
#pragma unroll
    for (int i = 0; i < 13; i++) {
        int og = tx + 32 * i;
        if (og < 400) {
            int mat = og / DD, o = og % DD;
            float b = g_bstack[og];
            float* base = g_proj + (size_t)mat * NN * DD;
#pragma unroll
            for (int j = 0; j < 4; j++) {
                int n = nb + ty * 4 + j;
                if (n < NN) base[(size_t)n * DD + o] = acc[j][i] + b;
            }
        }
    }
}

// in-degree histogram
__global__ void hist_kernel(const int* __restrict__ dst) {
    int e = blockIdx.x * blockDim.x + threadIdx.x;
    if (e < EE) atomicAdd(&g_cnt[dst[e]], 1);
}

// single-block exclusive scan of g_cnt -> g_row, g_cur ; g_row[NN] = EE
__global__ void scan_kernel() {
    __shared__ int wsum[32];
    __shared__ int carry_s;
    const int tid = threadIdx.x;
    const int lane = tid & 31, wid = tid >> 5;
    if (tid == 0) carry_s = 0;
    __syncthreads();
    for (int base = 0; base < NN; base += 1024) {
        int i = base + tid;
        int v = (i < NN) ? g_cnt[i] : 0;
        int incl = v;
#pragma unroll
        for (int o = 1; o < 32; o <<= 1) {
            int t = __shfl_up_sync(0xffffffffu, incl, o);
            if (lane >= o) incl += t;
        }
        if (lane == 31) wsum[wid] = incl;
        __syncthreads();
        if (wid == 0) {
            int wv = wsum[lane];
            int wincl = wv;
#pragma unroll
            for (int o = 1; o < 32; o <<= 1) {
                int t = __shfl_up_sync(0xffffffffu, wincl, o);
                if (lane >= o) wincl += t;
            }
            wsum[lane] = wincl - wv;
        }
        __syncthreads();
        int excl = carry_s + wsum[wid] + incl - v;
        if (i < NN) {
            g_row[i] = excl;
            g_cur[i] = excl;
        }
        __syncthreads();
        if (tid == 1023) carry_s = excl + v;
        __syncthreads();
    }
    if (tid == 0) g_row[NN] = carry_s;
}

__global__ void scatter_kernel(const int* __restrict__ src, const int* __restrict__ dst,
                               const int* __restrict__ et) {
    int e = blockIdx.x * blockDim.x + threadIdx.x;
    if (e >= EE) return;
    int d = dst[e];
    int pos = atomicAdd(&g_cur[d], 1);
    g_csrc[pos] = src[e];
    g_cet[pos] = et[e];
}

// Fused: per-warp per-dst: edge logits (K*relw*Q) + segment softmax + weighted V
// sum + gated combine + BN-stat accumulation.
__global__ __launch_bounds__(256) void fused_agg_kernel(const float* __restrict__ alpha) {
    __shared__ float satt[8][CAP];
    __shared__ float bsum[DD], bsq[DD];
    const int tid = threadIdx.x;
    if (tid < DD) { bsum[tid] = 0.f; bsq[tid] = 0.f; }
    __syncthreads();

    const int wid = tid >> 5, lane = tid & 31;
    const int node = blockIdx.x * 8 + wid;
    const bool active = (node < NN);
    const bool dl = (lane < 25);

    const float* S = g_proj;
    const float* K = g_proj + 1L * NN * DD;
    const float* Q = g_proj + 2L * NN * DD;
    const float* V = g_proj + 3L * NN * DD;

    float a = 1.f / (1.f + __expf(-alpha[0]));
    float4 acc = {0.f, 0.f, 0.f, 0.f};

    if (active) {
        const int s0 = g_row[node];
        const int deg = g_row[node + 1] - s0;

        float4 qv = {0.f, 0.f, 0.f, 0.f};
        if (dl) qv = *(const float4*)(Q + (size_t)node * DD + lane * 4);

        if (deg > 0) {
            float m = -1e30f;
            int i = 0;
            for (; i + 1 < deg; i += 2) {
                int sA = g_csrc[s0 + i], rA = g_cet[s0 + i];
                int sB = g_csrc[s0 + i + 1], rB = g_cet[s0 + i + 1];
                float pA = 0.f, pB = 0.f;
                if (dl) {
                    float4 kA = *(const float4*)(K + (size_t)sA * DD + lane * 4);
                    float4 wA = *(const float4*)(g_relw + rA * DD + lane * 4);
                    float4 kB = *(const float4*)(K + (size_t)sB * DD + lane * 4);
                    float4 wB = *(const float4*)(g_relw + rB * DD + lane * 4);
                    pA = kA.x * wA.x * qv.x + kA.y * wA.y * qv.y +
                         kA.z * wA.z * qv.z + kA.w * wA.w * qv.w;
                    pB = kB.x * wB.x * qv.x + kB.y * wB.y * qv.y +
                         kB.z * wB.z * qv.z + kB.w * wB.w * qv.w;
                }
#pragma unroll
                for (int o = 16; o; o >>= 1) {
                    pA += __shfl_xor_sync(0xffffffffu, pA, o);
                    pB += __shfl_xor_sync(0xffffffffu, pB, o);
                }
                m = fmaxf(m, fmaxf(pA, pB));
                if (lane == 0) {
                    if (i < CAP) satt[wid][i] = pA; else g_catt[s0 + i] = pA;
                    if (i + 1 < CAP) satt[wid][i + 1] = pB; else g_catt[s0 + i + 1] = pB;
                }
            }
            if (i < deg) {
                int sA = g_csrc[s0 + i], rA = g_cet[s0 + i];
                float pA = 0.f;
                if (dl) {
                    float4 kA = *(const float4*)(K + (size_t)sA * DD + lane * 4);
                    float4 wA = *(const float4*)(g_relw + rA * DD + lane * 4);
                    pA = kA.x * wA.x * qv.x + kA.y * wA.y * qv.y +
                         kA.z * wA.z * qv.z + kA.w * wA.w * qv.w;
                }
#pragma unroll
                for (int o = 16; o; o >>= 1) pA += __shfl_xor_sync(0xffffffffu, pA, o);
                m = fmaxf(m, pA);
                if (lane == 0) {
                    if (i < CAP) satt[wid][i] = pA; else g_catt[s0 + i] = pA;
                }
            }
            __syncwarp();

            // denominator
            float ssum = 0.f;
            for (int j = lane; j < deg; j += 32) {
                float av = (j < CAP) ? satt[wid][j] : g_catt[s0 + j];
                ssum += __expf(av - m);
            }
#pragma unroll
            for (int o = 16; o; o >>= 1) ssum += __shfl_xor_sync(0xffffffffu, ssum, o);
            float inv = 1.f / ssum;

            // weighted V accumulation, 2-way unrolled for MLP
            int j = 0;
            for (; j + 1 < deg; j += 2) {
                float aA = (j < CAP) ? satt[wid][j] : g_catt[s0 + j];
                float aB = (j + 1 < CAP) ? satt[wid][j + 1] : g_catt[s0 + j + 1];
                float wA = __expf(aA - m) * inv;
                float wB = __expf(aB - m) * inv;
                int sA = g_csrc[s0 + j];
                int sB = g_csrc[s0 + j + 1];
                if (dl) {
                    float4 vA = *(const float4*)(V + (size_t)sA * DD + lane * 4);
                    float4 vB = *(const float4*)(V + (size_t)sB * DD + lane * 4);
                    acc.x = fmaf(wA, vA.x, fmaf(wB, vB.x, acc.x));
                    acc.y = fmaf(wA, vA.y, fmaf(wB, vB.y, acc.y));
                    acc.z = fmaf(wA, vA.z, fmaf(wB, vB.z, acc.z));
                    acc.w = fmaf(wA, vA.w, fmaf(wB, vB.w, acc.w));
                }
            }
            if (j < deg) {
                float aA = (j < CAP) ? satt[wid][j] : g_catt[s0 + j];
                float wA = __expf(aA - m) * inv;
                int sA = g_csrc[s0 + j];
                if (dl) {
                    float4 vA = *(const float4*)(V + (size_t)sA * DD + lane * 4);
                    acc.x = fmaf(wA, vA.x, acc.x);
                    acc.y = fmaf(wA, vA.y, acc.y);
                    acc.z = fmaf(wA, vA.z, acc.z);
                    acc.w = fmaf(wA, vA.w, acc.w);
                }
            }
        }

        if (dl) {
            float4 sv = *(const float4*)(S + (size_t)node * DD + lane * 4);
            float b = 1.f - a;
            float4 o;
            o.x = a * sv.x + b * acc.x;
            o.y = a * sv.y + b * acc.y;
            o.z = a * sv.z + b * acc.z;
            o.w = a * sv.w + b * acc.w;
            *(float4*)(g_npre + (size_t)node * DD + lane * 4) = o;
            int c = lane * 4;
            atomicAdd(&bsum[c + 0], o.x); atomicAdd(&bsq[c + 0], o.x * o.x);
            atomicAdd(&bsum[c + 1], o.y); atomicAdd(&bsq[c + 1], o.y * o.y);
            atomicAdd(&bsum[c + 2], o.z); atomicAdd(&bsq[c + 2], o.z * o.z);
            atomicAdd(&bsum[c + 3], o.w); atomicAdd(&bsq[c + 3], o.w * o.w);
        }
    }

    __syncthreads();
    if (tid < DD) {
        atomicAdd(&g_colsum[tid], bsum[tid]);
        atomicAdd(&g_colsq[tid], bsq[tid]);
    }
}

__global__ void bnapply_kernel(const float* __restrict__ gamma, const float* __restrict__ beta,
                               float* __restrict__ out) {
    int idx = blockIdx.x * blockDim.x + threadIdx.x;
    if (idx >= NN * DD) return;
    int c = idx % DD;
    const float invN = 1.f / (float)NN;
    float mu = g_colsum[c] * invN;
    float var = g_colsq[c] * invN - mu * mu;
    float inv = rsqrtf(var + BN_EPS);
    float v = (g_npre[idx] - mu) * inv * gamma[c] + beta[c];
    out[idx] = tanhf(v);
}

// r_out = r_feats @ Wr^T + br
__global__ void rout_kernel(const float* __restrict__ r_feats, float* __restrict__ out) {
    int t = blockIdx.x * blockDim.x + threadIdx.x;
    if (t >= RR * DD) return;
    int r = t / DD, o = t % DD;
    const float* wt4 = g_wt + 4 * DD * DD;
    const float* x = r_feats + r * DD;
    float acc = g_bias[4 * DD + o];
#pragma unroll 4
    for (int k = 0; k < DD; k++) acc = fmaf(x[k], wt4[k * DD + o], acc);
    out[t] = acc;
}

// ---------------------------------------------------------------------------
extern "C" void kernel_launch(void* const* d_in, const int* in_sizes, int n_in,
                              void* d_out, int out_size) {
    const float* x       = (const float*)d_in[0];
    const float* r_feats = (const float*)d_in[1];
    const int*   src     = (const int*)d_in[2];
    const int*   dst     = (const int*)d_in[3];
    const int*   et      = (const int*)d_in[4];
    // d_in[5] = norm (unused by reference)
    const float* Ws_w = (const float*)d_in[6];
    const float* Ws_b = (const float*)d_in[7];
    const float* Wk_w = (const float*)d_in[8];
    const float* Wk_b = (const float*)d_in[9];
    const float* Wq_w = (const float*)d_in[10];
    const float* Wq_b = (const float*)d_in[11];
    const float* Wv_w = (const float*)d_in[12];
    const float* Wv_b = (const float*)d_in[13];
    const float* Wr_w = (const float*)d_in[14];
    const float* Wr_b = (const float*)d_in[15];
    const float* rel_att = (const float*)d_in[16];
    const float* w_comp  = (const float*)d_in[17];
    const float* alpha   = (const float*)d_in[18];
    // d_in[19] = loop_rel (only affects the dropped row)
    const float* gamma = (const float*)d_in[20];
    const float* beta  = (const float*)d_in[21];

    float* out_n = (float*)d_out;
    float* out_r = (float*)d_out + (out_size - RR * DD);

    zero_kernel<<<128, 256>>>();
    prep_kernel<<<(DD * 512 + 255) / 256, 256>>>(Ws_w, Ws_b, Wk_w, Wk_b, Wq_w, Wq_b,
                                                 Wv_w, Wv_b, Wr_w, Wr_b, w_comp, rel_att);
    hist_kernel<<<(EE + 255) / 256, 256>>>(dst);
    proj_kernel<<<(NN + 31) / 32, 256>>>(x);
    scan_kernel<<<1, 1024>>>();
    scatter_kernel<<<(EE + 255) / 256, 256>>>(src, dst, et);
    fused_agg_kernel<<<(NN + 7) / 8, 256>>>(alpha);
    bnapply_kernel<<<(NN * DD + 255) / 256, 256>>>(gamma, beta, out_n);
    rout_kernel<<<(RR * DD + 255) / 256, 256>>>(r_feats, out_r);
}